// round 3
// baseline (speedup 1.0000x reference)
#include <cuda_runtime.h>

// ---------------------------------------------------------------------------
// AlternatingHighwayLSTM  (S=256, B=64, IN=1024, H=512, L=8)
//
// Per layer:
//   1) proj_gemm:  proj = x @ w_x   (16384 x 3072) fp32 SGEMM, epilogue stores
//                  transposed g_proj[t][col][b] so recurrent loads coalesce.
//   2) lstm_layer: persistent kernel, 128 co-resident CTAs, 256 sequential
//                  steps with a software grid barrier per step.
// ---------------------------------------------------------------------------

#define S_LEN   256
#define BATCH   64
#define HID     512
#define NLAYER  8
#define G5      2560            // 5*H
#define PW      3072            // 6*H
#define MROWS   (S_LEN*BATCH)   // 16384
#define NBLK    128             // recurrent grid (<= SM count, 1 CTA/SM)

// ------------------------------- scratch -----------------------------------
__device__ __align__(16) float g_proj[(size_t)S_LEN * PW * BATCH];      // 201 MB
__device__ __align__(16) float g_act[2][(size_t)S_LEN * BATCH * HID];   // 67 MB
__device__ __align__(16) float g_hm[2][BATCH * HID];                    // h*mask
__device__ unsigned int           g_bar_count;
__device__ volatile unsigned int  g_bar_gen;

// --------------------------- grid-wide barrier ------------------------------
__device__ __forceinline__ void grid_barrier(unsigned nb) {
    __syncthreads();
    if (threadIdx.x == 0) {
        __threadfence();
        unsigned gen = g_bar_gen;
        if (atomicAdd(&g_bar_count, 1u) == nb - 1u) {
            atomicExch(&g_bar_count, 0u);
            __threadfence();
            g_bar_gen = gen + 1u;
        } else {
            while (g_bar_gen == gen) { __nanosleep(64); }
            __threadfence();
        }
    }
    __syncthreads();
}

// --------------------------- projection GEMM --------------------------------
// C(16384 x 3072) = A(16384 x K) * W(K x 3072), fp32.
// Block 256 threads, tile 128x128x8, 8x8 register micro-tile, smem double buf.
// Epilogue stores transposed: g_proj[t][col][b] with row m = t*64 + b.
__global__ __launch_bounds__(256, 2)
void proj_gemm(const float* __restrict__ Aext, int src_sel,
               const float* __restrict__ W, int K)
{
    const float* A = (src_sel < 0) ? Aext : g_act[src_sel];

    __shared__ float As[2][8][132];   // [buf][k][m] (padded)
    __shared__ float Bs[2][8][128];   // [buf][k][n]
    __shared__ float stage[32][130];  // epilogue transpose buffer

    const int bn = blockIdx.x;        // 0..23
    const int bm = blockIdx.y;        // 0..127
    const int tid = threadIdx.x;
    const int tx = tid & 15;          // n micro
    const int ty = tid >> 4;          // m micro

    const int arow = tid >> 1;            // 0..127
    const int acol = (tid & 1) * 4;       // 0 or 4
    const int brow = tid >> 5;            // 0..7
    const int bcol = (tid & 31) * 4;      // 0..124

    const float* Aptr = A + (size_t)(bm * 128 + arow) * K + acol;
    const float* Wptr = W + (size_t)brow * PW + bn * 128 + bcol;

    float acc[8][8];
#pragma unroll
    for (int i = 0; i < 8; ++i)
#pragma unroll
        for (int j = 0; j < 8; ++j) acc[i][j] = 0.f;

    float4 av = *(const float4*)Aptr;
    float4 bv = *(const float4*)Wptr;
    As[0][acol + 0][arow] = av.x;
    As[0][acol + 1][arow] = av.y;
    As[0][acol + 2][arow] = av.z;
    As[0][acol + 3][arow] = av.w;
    *(float4*)&Bs[0][brow][bcol] = bv;
    __syncthreads();

    const int KT = K >> 3;
    int buf = 0;
    for (int kt = 0; kt < KT; ++kt) {
        if (kt + 1 < KT) {
            av = *(const float4*)(Aptr + (kt + 1) * 8);
            bv = *(const float4*)(Wptr + (size_t)(kt + 1) * 8 * PW);
        }
#pragma unroll
        for (int kk = 0; kk < 8; ++kk) {
            float a[8], b[8];
            *(float4*)(a)     = *(const float4*)&As[buf][kk][ty * 8];
            *(float4*)(a + 4) = *(const float4*)&As[buf][kk][ty * 8 + 4];
            *(float4*)(b)     = *(const float4*)&Bs[buf][kk][tx * 8];
            *(float4*)(b + 4) = *(const float4*)&Bs[buf][kk][tx * 8 + 4];
#pragma unroll
            for (int i = 0; i < 8; ++i)
#pragma unroll
                for (int j = 0; j < 8; ++j)
                    acc[i][j] += a[i] * b[j];
        }
        if (kt + 1 < KT) {
            buf ^= 1;
            As[buf][acol + 0][arow] = av.x;
            As[buf][acol + 1][arow] = av.y;
            As[buf][acol + 2][arow] = av.z;
            As[buf][acol + 3][arow] = av.w;
            *(float4*)&Bs[buf][brow][bcol] = bv;
            __syncthreads();
        }
    }

    // epilogue: transpose through smem in 4 passes of 32 columns
#pragma unroll
    for (int p = 0; p < 4; ++p) {
        __syncthreads();
        if ((tx >> 2) == p) {
            const int txl = tx & 3;
#pragma unroll
            for (int i = 0; i < 8; ++i)
#pragma unroll
                for (int j = 0; j < 8; ++j)
                    stage[txl * 8 + j][ty * 8 + i] = acc[i][j];
        }
        __syncthreads();
        for (int idx = tid; idx < 32 * 128; idx += 256) {
            const int colL = idx >> 7;
            const int m    = idx & 127;
            const int col  = bn * 128 + p * 32 + colL;
            const int t_   = bm * 2 + (m >> 6);
            const int b_   = m & 63;
            g_proj[((size_t)t_ * PW + col) * BATCH + b_] = stage[colL][m];
        }
    }
}

// ------------------------- recurrent layer kernel ---------------------------
// Grid = 128 CTAs x 256 threads. CTA ct owns hidden indices [ct*4, ct*4+4).
// Thread t: b = t&63, jj = t>>6  -> all 5 gates for (b, jg).
// Smem: w_sh[5*4][512] (40 KB, loaded once) + h_sh[64][516] (staged each step).
#define WSH_FLOATS (5 * 4 * 512)
#define HSTRIDE    516
#define LSTM_SMEM  ((WSH_FLOATS + BATCH * HSTRIDE) * 4)

__device__ __forceinline__ float sigm(float x) { return 1.f / (1.f + __expf(-x)); }

__global__ __launch_bounds__(256, 1)
void lstm_layer(const float* __restrict__ wh,     // [512][2560]
                const float* __restrict__ bias_l, // [2560]
                const float* __restrict__ mask_l, // [64][512]
                float* __restrict__ outext,       // external out (last layer)
                int out_sel,                      // -1: outext, else g_act[sel]
                int reverse)
{
    float* outp = (out_sel < 0) ? outext : g_act[out_sel];

    extern __shared__ float sm[];
    float* w_sh = sm;                   // [ (g*4+jj) ][ k ]
    float* h_sh = sm + WSH_FLOATS;      // [ b ][ k ] stride 516

    const int tid = threadIdx.x;
    const int ct  = blockIdx.x;
    const int b   = tid & 63;
    const int jj  = tid >> 6;           // 0..3
    const int jg  = ct * 4 + jj;        // global hidden index

    for (int idx = tid; idx < WSH_FLOATS; idx += 256) {
        const int k = idx & 511;
        const int strip = idx >> 9;           // 0..19
        const int g  = strip >> 2;
        const int j2 = strip & 3;
        w_sh[strip * 512 + k] = wh[(size_t)k * G5 + g * HID + ct * 4 + j2];
    }

    float bb[5];
#pragma unroll
    for (int g = 0; g < 5; ++g) bb[g] = bias_l[g * HID + jg];
    const float mk = mask_l[b * HID + jg];

    float c = 0.f;
    g_hm[0][b * HID + jg] = 0.f;     // h0 = 0 (all (b,j) covered across CTAs)
    grid_barrier(NBLK);

    const float* hm_src = g_hm[0];
    float*       hm_dst = g_hm[1];

    const float4* wp[5];
#pragma unroll
    for (int g = 0; g < 5; ++g) wp[g] = (const float4*)&w_sh[(g * 4 + jj) * 512];

    for (int s = 0; s < S_LEN; ++s) {
        const int t = reverse ? (S_LEN - 1 - s) : s;

        // stage h*mask into smem (coalesced)
        const float4* src4 = (const float4*)hm_src;
        for (int idx = tid; idx < BATCH * 128; idx += 256) {
            const int bb_ = idx >> 7;
            const int kq  = idx & 127;
            float4 v = src4[bb_ * 128 + kq];
            *(float4*)&h_sh[bb_ * HSTRIDE + kq * 4] = v;
        }
        __syncthreads();

        float acc[5] = {0.f, 0.f, 0.f, 0.f, 0.f};
        const float4* hrow = (const float4*)&h_sh[b * HSTRIDE];
#pragma unroll 4
        for (int kq = 0; kq < 128; ++kq) {
            const float4 hv = hrow[kq];
#pragma unroll
            for (int g = 0; g < 5; ++g) {
                const float4 wv = wp[g][kq];
                acc[g] += hv.x * wv.x + hv.y * wv.y + hv.z * wv.z + hv.w * wv.w;
            }
        }

        const float* pt = g_proj + (size_t)t * PW * BATCH;
        const float zi = acc[0] + pt[(0 * HID + jg) * BATCH + b] + bb[0];
        const float zf = acc[1] + pt[(1 * HID + jg) * BATCH + b] + bb[1];
        const float zg = acc[2] + pt[(2 * HID + jg) * BATCH + b] + bb[2];
        const float zo = acc[3] + pt[(3 * HID + jg) * BATCH + b] + bb[3];
        const float zr = acc[4] + pt[(4 * HID + jg) * BATCH + b] + bb[4];
        const float lin = pt[(G5 + jg) * BATCH + b];

        const float iv = sigm(zi);
        const float fv = sigm(zf);
        const float gv = tanhf(zg);
        const float ov = sigm(zo);
        const float rv = sigm(zr);
        c = fv * c + iv * gv;
        const float hval = rv * (ov * tanhf(c)) + (1.f - rv) * lin;

        outp[(size_t)t * BATCH * HID + b * HID + jg] = hval;
        hm_dst[b * HID + jg] = hval * mk;

        grid_barrier(NBLK);   // publishes hm_dst; also protects h_sh reuse

        float* tmp = (float*)hm_src; hm_src = hm_dst; hm_dst = tmp;
    }
}

// ------------------------------ launcher ------------------------------------
extern "C" void kernel_launch(void* const* d_in, const int* in_sizes, int n_in,
                              void* d_out, int out_size)
{
    const float* x0   = (const float*)d_in[0];   // (256,64,1024)
    const float* w    = (const float*)d_in[1];   // flat weights
    const float* bias = (const float*)d_in[2];   // (8*2560)
    const float* mask = (const float*)d_in[3];   // (8,64,512)
    float* out = (float*)d_out;                  // (256,64,512)

    cudaFuncSetAttribute(lstm_layer, cudaFuncAttributeMaxDynamicSharedMemorySize,
                         LSTM_SMEM);

    size_t w_off = 0;
    int src_sel = -1;          // layer input: -1 = external x0, else g_act idx
    int K = 1024;
    for (int l = 0; l < NLAYER; ++l) {
        const float* wx = w + w_off; w_off += (size_t)K * PW;
        const float* wh = w + w_off; w_off += (size_t)HID * G5;

        proj_gemm<<<dim3(PW / 128, MROWS / 128), 256>>>(x0, src_sel, wx, K);

        const int out_sel = (l == NLAYER - 1) ? -1 : (l & 1);
        lstm_layer<<<NBLK, 256, LSTM_SMEM>>>(wh,
                                             bias + (size_t)l * G5,
                                             mask + (size_t)l * BATCH * HID,
                                             out, out_sel,
                                             l & 1);
        src_sel = (l & 1);
        K = HID;
    }
}

// round 4
// speedup vs baseline: 1.0005x; 1.0005x over previous
#include <cuda_runtime.h>

// ---------------------------------------------------------------------------
// AlternatingHighwayLSTM  (S=256, B=64, IN=1024, H=512, L=8)
//
// Per layer:
//   1) proj_gemm:  proj = x @ w_x   (16384 x 3072) fp32 SGEMM, epilogue stores
//                  transposed g_proj[t][col][b] so recurrent loads coalesce.
//   2) lstm_layer: persistent kernel, 128 co-resident CTAs, 256 sequential
//                  steps with a software grid barrier per step.
// ---------------------------------------------------------------------------

#define S_LEN   256
#define BATCH   64
#define HID     512
#define NLAYER  8
#define G5      2560            // 5*H
#define PW      3072            // 6*H
#define MROWS   (S_LEN*BATCH)   // 16384
#define NBLK    128             // recurrent grid (<= SM count, 1 CTA/SM)

// ------------------------------- scratch -----------------------------------
__device__ __align__(16) float g_proj[(size_t)S_LEN * PW * BATCH];      // 201 MB
__device__ __align__(16) float g_act[2][(size_t)S_LEN * BATCH * HID];   // 67 MB
__device__ __align__(16) float g_hm[2][BATCH * HID];                    // h*mask
__device__ unsigned int           g_bar_count;
__device__ volatile unsigned int  g_bar_gen;

// --------------------------- grid-wide barrier ------------------------------
__device__ __forceinline__ void grid_barrier(unsigned nb) {
    __syncthreads();
    if (threadIdx.x == 0) {
        __threadfence();
        unsigned gen = g_bar_gen;
        if (atomicAdd(&g_bar_count, 1u) == nb - 1u) {
            atomicExch(&g_bar_count, 0u);
            __threadfence();
            g_bar_gen = gen + 1u;
        } else {
            while (g_bar_gen == gen) { __nanosleep(64); }
            __threadfence();
        }
    }
    __syncthreads();
}

// --------------------------- projection GEMM --------------------------------
// C(16384 x 3072) = A(16384 x K) * W(K x 3072), fp32.
// Block 256 threads, tile 128x128x8, 8x8 register micro-tile, smem double buf.
// Epilogue stores transposed: g_proj[t][col][b] with row m = t*64 + b.
__global__ __launch_bounds__(256, 2)
void proj_gemm(const float* __restrict__ Aext, int src_sel,
               const float* __restrict__ W, int K)
{
    const float* A = (src_sel < 0) ? Aext : g_act[src_sel];

    __shared__ float As[2][8][132];   // [buf][k][m] (padded)
    __shared__ float Bs[2][8][128];   // [buf][k][n]
    __shared__ float stage[32][130];  // epilogue transpose buffer

    const int bn = blockIdx.x;        // 0..23
    const int bm = blockIdx.y;        // 0..127
    const int tid = threadIdx.x;
    const int tx = tid & 15;          // n micro
    const int ty = tid >> 4;          // m micro

    const int arow = tid >> 1;            // 0..127
    const int acol = (tid & 1) * 4;       // 0 or 4
    const int brow = tid >> 5;            // 0..7
    const int bcol = (tid & 31) * 4;      // 0..124

    const float* Aptr = A + (size_t)(bm * 128 + arow) * K + acol;
    const float* Wptr = W + (size_t)brow * PW + bn * 128 + bcol;

    float acc[8][8];
#pragma unroll
    for (int i = 0; i < 8; ++i)
#pragma unroll
        for (int j = 0; j < 8; ++j) acc[i][j] = 0.f;

    float4 av = *(const float4*)Aptr;
    float4 bv = *(const float4*)Wptr;
    As[0][acol + 0][arow] = av.x;
    As[0][acol + 1][arow] = av.y;
    As[0][acol + 2][arow] = av.z;
    As[0][acol + 3][arow] = av.w;
    *(float4*)&Bs[0][brow][bcol] = bv;
    __syncthreads();

    const int KT = K >> 3;
    int buf = 0;
    for (int kt = 0; kt < KT; ++kt) {
        if (kt + 1 < KT) {
            av = *(const float4*)(Aptr + (kt + 1) * 8);
            bv = *(const float4*)(Wptr + (size_t)(kt + 1) * 8 * PW);
        }
#pragma unroll
        for (int kk = 0; kk < 8; ++kk) {
            float a[8], b[8];
            *(float4*)(a)     = *(const float4*)&As[buf][kk][ty * 8];
            *(float4*)(a + 4) = *(const float4*)&As[buf][kk][ty * 8 + 4];
            *(float4*)(b)     = *(const float4*)&Bs[buf][kk][tx * 8];
            *(float4*)(b + 4) = *(const float4*)&Bs[buf][kk][tx * 8 + 4];
#pragma unroll
            for (int i = 0; i < 8; ++i)
#pragma unroll
                for (int j = 0; j < 8; ++j)
                    acc[i][j] += a[i] * b[j];
        }
        if (kt + 1 < KT) {
            buf ^= 1;
            As[buf][acol + 0][arow] = av.x;
            As[buf][acol + 1][arow] = av.y;
            As[buf][acol + 2][arow] = av.z;
            As[buf][acol + 3][arow] = av.w;
            *(float4*)&Bs[buf][brow][bcol] = bv;
            __syncthreads();
        }
    }

    // epilogue: transpose through smem in 4 passes of 32 columns
#pragma unroll
    for (int p = 0; p < 4; ++p) {
        __syncthreads();
        if ((tx >> 2) == p) {
            const int txl = tx & 3;
#pragma unroll
            for (int i = 0; i < 8; ++i)
#pragma unroll
                for (int j = 0; j < 8; ++j)
                    stage[txl * 8 + j][ty * 8 + i] = acc[i][j];
        }
        __syncthreads();
        for (int idx = tid; idx < 32 * 128; idx += 256) {
            const int colL = idx >> 7;
            const int m    = idx & 127;
            const int col  = bn * 128 + p * 32 + colL;
            const int t_   = bm * 2 + (m >> 6);
            const int b_   = m & 63;
            g_proj[((size_t)t_ * PW + col) * BATCH + b_] = stage[colL][m];
        }
    }
}

// ------------------------- recurrent layer kernel ---------------------------
// Grid = 128 CTAs x 256 threads. CTA ct owns hidden indices [ct*4, ct*4+4).
// Thread t: b = t&63, jj = t>>6  -> all 5 gates for (b, jg).
// Smem: w_sh[5*4][512] (40 KB, loaded once) + h_sh[64][516] (staged each step).
#define WSH_FLOATS (5 * 4 * 512)
#define HSTRIDE    516
#define LSTM_SMEM  ((WSH_FLOATS + BATCH * HSTRIDE) * 4)

__device__ __forceinline__ float sigm(float x) { return 1.f / (1.f + __expf(-x)); }

__global__ __launch_bounds__(256, 1)
void lstm_layer(const float* __restrict__ wh,     // [512][2560]
                const float* __restrict__ bias_l, // [2560]
                const float* __restrict__ mask_l, // [64][512]
                float* __restrict__ outext,       // external out (last layer)
                int out_sel,                      // -1: outext, else g_act[sel]
                int reverse)
{
    float* outp = (out_sel < 0) ? outext : g_act[out_sel];

    extern __shared__ float sm[];
    float* w_sh = sm;                   // [ (g*4+jj) ][ k ]
    float* h_sh = sm + WSH_FLOATS;      // [ b ][ k ] stride 516

    const int tid = threadIdx.x;
    const int ct  = blockIdx.x;
    const int b   = tid & 63;
    const int jj  = tid >> 6;           // 0..3
    const int jg  = ct * 4 + jj;        // global hidden index

    for (int idx = tid; idx < WSH_FLOATS; idx += 256) {
        const int k = idx & 511;
        const int strip = idx >> 9;           // 0..19
        const int g  = strip >> 2;
        const int j2 = strip & 3;
        w_sh[strip * 512 + k] = wh[(size_t)k * G5 + g * HID + ct * 4 + j2];
    }

    float bb[5];
#pragma unroll
    for (int g = 0; g < 5; ++g) bb[g] = bias_l[g * HID + jg];
    const float mk = mask_l[b * HID + jg];

    float c = 0.f;
    g_hm[0][b * HID + jg] = 0.f;     // h0 = 0 (all (b,j) covered across CTAs)
    grid_barrier(NBLK);

    const float* hm_src = g_hm[0];
    float*       hm_dst = g_hm[1];

    const float4* wp[5];
#pragma unroll
    for (int g = 0; g < 5; ++g) wp[g] = (const float4*)&w_sh[(g * 4 + jj) * 512];

    for (int s = 0; s < S_LEN; ++s) {
        const int t = reverse ? (S_LEN - 1 - s) : s;

        // stage h*mask into smem (coalesced)
        const float4* src4 = (const float4*)hm_src;
        for (int idx = tid; idx < BATCH * 128; idx += 256) {
            const int bb_ = idx >> 7;
            const int kq  = idx & 127;
            float4 v = src4[bb_ * 128 + kq];
            *(float4*)&h_sh[bb_ * HSTRIDE + kq * 4] = v;
        }
        __syncthreads();

        float acc[5] = {0.f, 0.f, 0.f, 0.f, 0.f};
        const float4* hrow = (const float4*)&h_sh[b * HSTRIDE];
#pragma unroll 4
        for (int kq = 0; kq < 128; ++kq) {
            const float4 hv = hrow[kq];
#pragma unroll
            for (int g = 0; g < 5; ++g) {
                const float4 wv = wp[g][kq];
                acc[g] += hv.x * wv.x + hv.y * wv.y + hv.z * wv.z + hv.w * wv.w;
            }
        }

        const float* pt = g_proj + (size_t)t * PW * BATCH;
        const float zi = acc[0] + pt[(0 * HID + jg) * BATCH + b] + bb[0];
        const float zf = acc[1] + pt[(1 * HID + jg) * BATCH + b] + bb[1];
        const float zg = acc[2] + pt[(2 * HID + jg) * BATCH + b] + bb[2];
        const float zo = acc[3] + pt[(3 * HID + jg) * BATCH + b] + bb[3];
        const float zr = acc[4] + pt[(4 * HID + jg) * BATCH + b] + bb[4];
        const float lin = pt[(G5 + jg) * BATCH + b];

        const float iv = sigm(zi);
        const float fv = sigm(zf);
        const float gv = tanhf(zg);
        const float ov = sigm(zo);
        const float rv = sigm(zr);
        c = fv * c + iv * gv;
        const float hval = rv * (ov * tanhf(c)) + (1.f - rv) * lin;

        outp[(size_t)t * BATCH * HID + b * HID + jg] = hval;
        hm_dst[b * HID + jg] = hval * mk;

        grid_barrier(NBLK);   // publishes hm_dst; also protects h_sh reuse

        float* tmp = (float*)hm_src; hm_src = hm_dst; hm_dst = tmp;
    }
}

// ------------------------------ launcher ------------------------------------
extern "C" void kernel_launch(void* const* d_in, const int* in_sizes, int n_in,
                              void* d_out, int out_size)
{
    const float* x0   = (const float*)d_in[0];   // (256,64,1024)
    const float* w    = (const float*)d_in[1];   // flat weights
    const float* bias = (const float*)d_in[2];   // (8*2560)
    const float* mask = (const float*)d_in[3];   // (8,64,512)
    float* out = (float*)d_out;                  // (256,64,512)

    cudaFuncSetAttribute(lstm_layer, cudaFuncAttributeMaxDynamicSharedMemorySize,
                         LSTM_SMEM);

    size_t w_off = 0;
    int src_sel = -1;          // layer input: -1 = external x0, else g_act idx
    int K = 1024;
    for (int l = 0; l < NLAYER; ++l) {
        const float* wx = w + w_off; w_off += (size_t)K * PW;
        const float* wh = w + w_off; w_off += (size_t)HID * G5;

        proj_gemm<<<dim3(PW / 128, MROWS / 128), 256>>>(x0, src_sel, wx, K);

        const int out_sel = (l == NLAYER - 1) ? -1 : (l & 1);
        lstm_layer<<<NBLK, 256, LSTM_SMEM>>>(wh,
                                             bias + (size_t)l * G5,
                                             mask + (size_t)l * BATCH * HID,
                                             out, out_sel,
                                             l & 1);
        src_sel = (l & 1);
        K = HID;
    }
}

// round 5
// speedup vs baseline: 1.0009x; 1.0003x over previous
#include <cuda_runtime.h>

// ---------------------------------------------------------------------------
// AlternatingHighwayLSTM  (S=256, B=64, IN=1024, H=512, L=8)
//
// Per layer:
//   1) proj_gemm:  proj = x @ w_x   (16384 x 3072) fp32 SGEMM, epilogue stores
//                  transposed g_proj[t][col][b] so recurrent loads coalesce.
//   2) lstm_layer: persistent kernel, 128 co-resident CTAs, 256 sequential
//                  steps with a software grid barrier per step.
// ---------------------------------------------------------------------------

#define S_LEN   256
#define BATCH   64
#define HID     512
#define NLAYER  8
#define G5      2560            // 5*H
#define PW      3072            // 6*H
#define MROWS   (S_LEN*BATCH)   // 16384
#define NBLK    128             // recurrent grid (<= SM count, 1 CTA/SM)

// ------------------------------- scratch -----------------------------------
__device__ __align__(16) float g_proj[(size_t)S_LEN * PW * BATCH];      // 201 MB
__device__ __align__(16) float g_act[2][(size_t)S_LEN * BATCH * HID];   // 67 MB
__device__ __align__(16) float g_hm[2][BATCH * HID];                    // h*mask
__device__ unsigned int           g_bar_count;
__device__ volatile unsigned int  g_bar_gen;

// --------------------------- grid-wide barrier ------------------------------
__device__ __forceinline__ void grid_barrier(unsigned nb) {
    __syncthreads();
    if (threadIdx.x == 0) {
        __threadfence();
        unsigned gen = g_bar_gen;
        if (atomicAdd(&g_bar_count, 1u) == nb - 1u) {
            atomicExch(&g_bar_count, 0u);
            __threadfence();
            g_bar_gen = gen + 1u;
        } else {
            while (g_bar_gen == gen) { __nanosleep(64); }
            __threadfence();
        }
    }
    __syncthreads();
}

// --------------------------- projection GEMM --------------------------------
// C(16384 x 3072) = A(16384 x K) * W(K x 3072), fp32.
// Block 256 threads, tile 128x128x8, 8x8 register micro-tile, smem double buf.
// Epilogue stores transposed: g_proj[t][col][b] with row m = t*64 + b.
__global__ __launch_bounds__(256, 2)
void proj_gemm(const float* __restrict__ Aext, int src_sel,
               const float* __restrict__ W, int K)
{
    const float* A = (src_sel < 0) ? Aext : g_act[src_sel];

    __shared__ float As[2][8][132];   // [buf][k][m] (padded)
    __shared__ float Bs[2][8][128];   // [buf][k][n]
    __shared__ float stage[32][130];  // epilogue transpose buffer

    const int bn = blockIdx.x;        // 0..23
    const int bm = blockIdx.y;        // 0..127
    const int tid = threadIdx.x;
    const int tx = tid & 15;          // n micro
    const int ty = tid >> 4;          // m micro

    const int arow = tid >> 1;            // 0..127
    const int acol = (tid & 1) * 4;       // 0 or 4
    const int brow = tid >> 5;            // 0..7
    const int bcol = (tid & 31) * 4;      // 0..124

    const float* Aptr = A + (size_t)(bm * 128 + arow) * K + acol;
    const float* Wptr = W + (size_t)brow * PW + bn * 128 + bcol;

    float acc[8][8];
#pragma unroll
    for (int i = 0; i < 8; ++i)
#pragma unroll
        for (int j = 0; j < 8; ++j) acc[i][j] = 0.f;

    float4 av = *(const float4*)Aptr;
    float4 bv = *(const float4*)Wptr;
    As[0][acol + 0][arow] = av.x;
    As[0][acol + 1][arow] = av.y;
    As[0][acol + 2][arow] = av.z;
    As[0][acol + 3][arow] = av.w;
    *(float4*)&Bs[0][brow][bcol] = bv;
    __syncthreads();

    const int KT = K >> 3;
    int buf = 0;
    for (int kt = 0; kt < KT; ++kt) {
        if (kt + 1 < KT) {
            av = *(const float4*)(Aptr + (kt + 1) * 8);
            bv = *(const float4*)(Wptr + (size_t)(kt + 1) * 8 * PW);
        }
#pragma unroll
        for (int kk = 0; kk < 8; ++kk) {
            float a[8], b[8];
            *(float4*)(a)     = *(const float4*)&As[buf][kk][ty * 8];
            *(float4*)(a + 4) = *(const float4*)&As[buf][kk][ty * 8 + 4];
            *(float4*)(b)     = *(const float4*)&Bs[buf][kk][tx * 8];
            *(float4*)(b + 4) = *(const float4*)&Bs[buf][kk][tx * 8 + 4];
#pragma unroll
            for (int i = 0; i < 8; ++i)
#pragma unroll
                for (int j = 0; j < 8; ++j)
                    acc[i][j] += a[i] * b[j];
        }
        if (kt + 1 < KT) {
            buf ^= 1;
            As[buf][acol + 0][arow] = av.x;
            As[buf][acol + 1][arow] = av.y;
            As[buf][acol + 2][arow] = av.z;
            As[buf][acol + 3][arow] = av.w;
            *(float4*)&Bs[buf][brow][bcol] = bv;
            __syncthreads();
        }
    }

    // epilogue: transpose through smem in 4 passes of 32 columns
#pragma unroll
    for (int p = 0; p < 4; ++p) {
        __syncthreads();
        if ((tx >> 2) == p) {
            const int txl = tx & 3;
#pragma unroll
            for (int i = 0; i < 8; ++i)
#pragma unroll
                for (int j = 0; j < 8; ++j)
                    stage[txl * 8 + j][ty * 8 + i] = acc[i][j];
        }
        __syncthreads();
        for (int idx = tid; idx < 32 * 128; idx += 256) {
            const int colL = idx >> 7;
            const int m    = idx & 127;
            const int col  = bn * 128 + p * 32 + colL;
            const int t_   = bm * 2 + (m >> 6);
            const int b_   = m & 63;
            g_proj[((size_t)t_ * PW + col) * BATCH + b_] = stage[colL][m];
        }
    }
}

// ------------------------- recurrent layer kernel ---------------------------
// Grid = 128 CTAs x 256 threads. CTA ct owns hidden indices [ct*4, ct*4+4).
// Thread t: b = t&63, jj = t>>6  -> all 5 gates for (b, jg).
// Smem: w_sh[5*4][512] (40 KB, loaded once) + h_sh[64][516] (staged each step).
#define WSH_FLOATS (5 * 4 * 512)
#define HSTRIDE    516
#define LSTM_SMEM  ((WSH_FLOATS + BATCH * HSTRIDE) * 4)

__device__ __forceinline__ float sigm(float x) { return 1.f / (1.f + __expf(-x)); }

__global__ __launch_bounds__(256, 1)
void lstm_layer(const float* __restrict__ wh,     // [512][2560]
                const float* __restrict__ bias_l, // [2560]
                const float* __restrict__ mask_l, // [64][512]
                float* __restrict__ outext,       // external out (last layer)
                int out_sel,                      // -1: outext, else g_act[sel]
                int reverse)
{
    float* outp = (out_sel < 0) ? outext : g_act[out_sel];

    extern __shared__ float sm[];
    float* w_sh = sm;                   // [ (g*4+jj) ][ k ]
    float* h_sh = sm + WSH_FLOATS;      // [ b ][ k ] stride 516

    const int tid = threadIdx.x;
    const int ct  = blockIdx.x;
    const int b   = tid & 63;
    const int jj  = tid >> 6;           // 0..3
    const int jg  = ct * 4 + jj;        // global hidden index

    for (int idx = tid; idx < WSH_FLOATS; idx += 256) {
        const int k = idx & 511;
        const int strip = idx >> 9;           // 0..19
        const int g  = strip >> 2;
        const int j2 = strip & 3;
        w_sh[strip * 512 + k] = wh[(size_t)k * G5 + g * HID + ct * 4 + j2];
    }

    float bb[5];
#pragma unroll
    for (int g = 0; g < 5; ++g) bb[g] = bias_l[g * HID + jg];
    const float mk = mask_l[b * HID + jg];

    float c = 0.f;
    g_hm[0][b * HID + jg] = 0.f;     // h0 = 0 (all (b,j) covered across CTAs)
    grid_barrier(NBLK);

    const float* hm_src = g_hm[0];
    float*       hm_dst = g_hm[1];

    const float4* wp[5];
#pragma unroll
    for (int g = 0; g < 5; ++g) wp[g] = (const float4*)&w_sh[(g * 4 + jj) * 512];

    for (int s = 0; s < S_LEN; ++s) {
        const int t = reverse ? (S_LEN - 1 - s) : s;

        // stage h*mask into smem (coalesced)
        const float4* src4 = (const float4*)hm_src;
        for (int idx = tid; idx < BATCH * 128; idx += 256) {
            const int bb_ = idx >> 7;
            const int kq  = idx & 127;
            float4 v = src4[bb_ * 128 + kq];
            *(float4*)&h_sh[bb_ * HSTRIDE + kq * 4] = v;
        }
        __syncthreads();

        float acc[5] = {0.f, 0.f, 0.f, 0.f, 0.f};
        const float4* hrow = (const float4*)&h_sh[b * HSTRIDE];
#pragma unroll 4
        for (int kq = 0; kq < 128; ++kq) {
            const float4 hv = hrow[kq];
#pragma unroll
            for (int g = 0; g < 5; ++g) {
                const float4 wv = wp[g][kq];
                acc[g] += hv.x * wv.x + hv.y * wv.y + hv.z * wv.z + hv.w * wv.w;
            }
        }

        const float* pt = g_proj + (size_t)t * PW * BATCH;
        const float zi = acc[0] + pt[(0 * HID + jg) * BATCH + b] + bb[0];
        const float zf = acc[1] + pt[(1 * HID + jg) * BATCH + b] + bb[1];
        const float zg = acc[2] + pt[(2 * HID + jg) * BATCH + b] + bb[2];
        const float zo = acc[3] + pt[(3 * HID + jg) * BATCH + b] + bb[3];
        const float zr = acc[4] + pt[(4 * HID + jg) * BATCH + b] + bb[4];
        const float lin = pt[(G5 + jg) * BATCH + b];

        const float iv = sigm(zi);
        const float fv = sigm(zf);
        const float gv = tanhf(zg);
        const float ov = sigm(zo);
        const float rv = sigm(zr);
        c = fv * c + iv * gv;
        const float hval = rv * (ov * tanhf(c)) + (1.f - rv) * lin;

        outp[(size_t)t * BATCH * HID + b * HID + jg] = hval;
        hm_dst[b * HID + jg] = hval * mk;

        grid_barrier(NBLK);   // publishes hm_dst; also protects h_sh reuse

        float* tmp = (float*)hm_src; hm_src = hm_dst; hm_dst = tmp;
    }
}

// ------------------------------ launcher ------------------------------------
extern "C" void kernel_launch(void* const* d_in, const int* in_sizes, int n_in,
                              void* d_out, int out_size)
{
    const float* x0   = (const float*)d_in[0];   // (256,64,1024)
    const float* w    = (const float*)d_in[1];   // flat weights
    const float* bias = (const float*)d_in[2];   // (8*2560)
    const float* mask = (const float*)d_in[3];   // (8,64,512)
    float* out = (float*)d_out;                  // (256,64,512)

    cudaFuncSetAttribute(lstm_layer, cudaFuncAttributeMaxDynamicSharedMemorySize,
                         LSTM_SMEM);

    size_t w_off = 0;
    int src_sel = -1;          // layer input: -1 = external x0, else g_act idx
    int K = 1024;
    for (int l = 0; l < NLAYER; ++l) {
        const float* wx = w + w_off; w_off += (size_t)K * PW;
        const float* wh = w + w_off; w_off += (size_t)HID * G5;

        proj_gemm<<<dim3(PW / 128, MROWS / 128), 256>>>(x0, src_sel, wx, K);

        const int out_sel = (l == NLAYER - 1) ? -1 : (l & 1);
        lstm_layer<<<NBLK, 256, LSTM_SMEM>>>(wh,
                                             bias + (size_t)l * G5,
                                             mask + (size_t)l * BATCH * HID,
                                             out, out_sel,
                                             l & 1);
        src_sel = (l & 1);
        K = HID;
    }
}